// round 2
// baseline (speedup 1.0000x reference)
#include <cuda_runtime.h>

// 15x15 separable Gaussian, 8192x8192 f32, reflect pad, stride 1.
// Fused separable conv: vertical (packed f32x2, register sliding window,
// global -> smem) then horizontal (scalar FMA, register window, smem -> global).

#define IMW 8192
#define IMH 8192
#define TX  112          // output tile width
#define TY  64           // output tile height
#define PX  128          // padded tile width in vbuf (halo 8 each side)
#define VSTRIDE 132      // vbuf row stride (floats), padded vs 128 to dodge bank conflicts
#define R   7            // kernel radius

__device__ __forceinline__ int refl(int i) {
    i = (i < 0) ? -i : i;
    return (i >= IMW) ? (2 * IMW - 2 - i) : i;
}

__device__ __forceinline__ float2 ffma2(float2 a, float2 b, float2 c) {
    unsigned long long ua = *reinterpret_cast<unsigned long long*>(&a);
    unsigned long long ub = *reinterpret_cast<unsigned long long*>(&b);
    unsigned long long uc = *reinterpret_cast<unsigned long long*>(&c);
    unsigned long long ud;
    asm("fma.rn.f32x2 %0, %1, %2, %3;" : "=l"(ud) : "l"(ua), "l"(ub), "l"(uc));
    return *reinterpret_cast<float2*>(&ud);
}

__device__ __forceinline__ float2 fmul2(float2 a, float2 b) {
    unsigned long long ua = *reinterpret_cast<unsigned long long*>(&a);
    unsigned long long ub = *reinterpret_cast<unsigned long long*>(&b);
    unsigned long long ud;
    asm("mul.rn.f32x2 %0, %1, %2;" : "=l"(ud) : "l"(ua), "l"(ub));
    return *reinterpret_cast<float2*>(&ud);
}

__global__ __launch_bounds__(256, 3)
void gauss_sep_kernel(const float* __restrict__ img,
                      const float* __restrict__ K,
                      float* __restrict__ out) {
    __shared__ float s_k1[32];  // [0..14] = ky (row sums), [16..30] = kx (col sums)
    __shared__ __align__(16) float vbuf[TY * VSTRIDE];

    const int tid = threadIdx.x;

    // ---- phase 0: recover 1-D factors from the rank-1 2-D kernel ----
    if (tid < 32) {
        float s = 0.0f;
        if (tid < 15) {
            #pragma unroll
            for (int j = 0; j < 15; j++) s += K[tid * 15 + j];
        } else if (tid >= 16 && tid < 31) {
            const int c = tid - 16;
            #pragma unroll
            for (int i = 0; i < 15; i++) s += K[i * 15 + c];
        }
        s_k1[tid] = s;
    }
    __syncthreads();

    const int bx = blockIdx.x;
    const int by = blockIdx.y;

    // ---- phase 1: vertical conv (packed f32x2), global -> vbuf ----
    {
        const int pc = tid & 63;        // float2 column 0..63
        const int g  = tid >> 6;        // y-group 0..3 (16 vbuf rows each)
        const int gxp = bx * TX - 8 + 2 * pc;          // global col of pair (even)
        const bool xok = (gxp >= 0) && (gxp + 1 < IMW);
        const int rx0 = refl(gxp);
        const int rx1 = refl(gxp + 1);
        const int gy0 = by * TY + 16 * g;              // first output row of group

        float2 kyv[15];
        #pragma unroll
        for (int i = 0; i < 15; i++) {
            const float k = s_k1[i];
            kyv[i] = make_float2(k, k);
        }

        float2 win[15];
        // warm-up: input rows gy0-7 .. gy0+6
        #pragma unroll
        for (int i = 0; i < 14; i++) {
            const int ry = refl(gy0 - R + i);
            const float* rowp = img + ry * IMW;
            if (xok) {
                win[i] = *reinterpret_cast<const float2*>(rowp + gxp);
            } else {
                win[i].x = rowp[rx0];
                win[i].y = rowp[rx1];
            }
        }
        // 16 sliding steps
        #pragma unroll
        for (int s = 0; s < 16; s++) {
            const int ry = refl(gy0 + R + s);
            const float* rowp = img + ry * IMW;
            float2 nv;
            if (xok) {
                nv = *reinterpret_cast<const float2*>(rowp + gxp);
            } else {
                nv.x = rowp[rx0];
                nv.y = rowp[rx1];
            }
            win[(14 + s) % 15] = nv;

            float2 acc = fmul2(kyv[0], win[s % 15]);
            #pragma unroll
            for (int i = 1; i < 15; i++)
                acc = ffma2(kyv[i], win[(s + i) % 15], acc);

            *reinterpret_cast<float2*>(&vbuf[(16 * g + s) * VSTRIDE + 2 * pc]) = acc;
        }
    }
    __syncthreads();

    // ---- phase 2: horizontal conv (scalar FMA, register window), vbuf -> out ----
    {
        float kx[15];
        #pragma unroll
        for (int i = 0; i < 15; i++) kx[i] = s_k1[16 + i];

        #pragma unroll
        for (int r = 0; r < 7; r++) {
            const int id  = r * 256 + tid;      // 0..1791 run id
            const int row = id / 28;            // 28 runs of 4 per row
            const int x0  = (id - row * 28) * 4;

            const float* vp = &vbuf[row * VSTRIDE + x0];
            float w[20];
            #pragma unroll
            for (int j = 0; j < 20; j += 4) {
                const float4 t = *reinterpret_cast<const float4*>(vp + j);
                w[j] = t.x; w[j + 1] = t.y; w[j + 2] = t.z; w[j + 3] = t.w;
            }
            // output x (tile) maps to vbuf col x+1 .. x+15 for the 15 taps
            float o0 = kx[0] * w[1];
            float o1 = kx[0] * w[2];
            float o2 = kx[0] * w[3];
            float o3 = kx[0] * w[4];
            #pragma unroll
            for (int i = 1; i < 15; i++) {
                o0 = fmaf(kx[i], w[1 + i], o0);
                o1 = fmaf(kx[i], w[2 + i], o1);
                o2 = fmaf(kx[i], w[3 + i], o2);
                o3 = fmaf(kx[i], w[4 + i], o3);
            }

            const int gx0 = bx * TX + x0;
            const int gy  = by * TY + row;
            if (gx0 + 3 < IMW) {
                *reinterpret_cast<float4*>(&out[gy * IMW + gx0]) =
                    make_float4(o0, o1, o2, o3);
            }
        }
    }
}

extern "C" void kernel_launch(void* const* d_in, const int* in_sizes, int n_in,
                              void* d_out, int out_size) {
    const float* img = (const float*)d_in[0];
    const float* K   = (const float*)d_in[1];
    // d_in[2] is stride (== 1 for this problem); output size confirms stride 1.
    float* out = (float*)d_out;

    dim3 grid((IMW + TX - 1) / TX, IMH / TY);
    gauss_sep_kernel<<<grid, 256>>>(img, K, out);
}